// round 4
// baseline (speedup 1.0000x reference)
#include <cuda_runtime.h>
#include <stdint.h>

#define BATCH 8192
#define IN_F  16384
#define HID   384
#define NOUT  10

// ---------------- GEMM tiling ----------------------------------------------
#define CTA_M  64
#define KD     128              // k-depth per stage (int8 bytes per row)
#define RS     144              // padded smem row stride (conflict-free ldmatrix)
#define A_ST   (CTA_M * RS)     // 9216
#define B_ST   (HID * RS)       // 55296
#define STAGE  (A_ST + B_ST)    // 64512
#define NSTG   3
#define SMEMSZ (NSTG * STAGE)   // 193536
#define NS     (IN_F / KD)      // 128 k-stages

// ---------------- scratch globals ------------------------------------------
__device__ int8_t    g_xb[(size_t)BATCH * IN_F];   // 128 MB sign-int8 x
__device__ int8_t    g_wb[(size_t)HID * IN_F];     // 6 MB sign-int8 W1
__device__ short     g_h[(size_t)BATCH * HID];     // 6.3 MB hidden pre-BN
__device__ long long g_sum[HID];
__device__ long long g_sumsq[HID];
__device__ float     g_A[HID];
__device__ float     g_B[HID];

// ---------------- PTX helpers ----------------------------------------------
__device__ __forceinline__ uint32_t smem_u32(const void* p) {
    uint32_t a;
    asm("{ .reg .u64 t; cvta.to.shared.u64 t, %1; cvt.u32.u64 %0, t; }"
        : "=r"(a) : "l"(p));
    return a;
}
#define CP16(s, g) \
    asm volatile("{ .reg .u64 gp; cvta.to.global.u64 gp, %1; " \
                 "cp.async.cg.shared.global [%0], [gp], 16; }" \
                 :: "r"(s), "l"(g) : "memory")
#define CPCOMMIT() asm volatile("cp.async.commit_group;" ::: "memory")
#define CPWAIT2()  asm volatile("cp.async.wait_group 2;" ::: "memory")
#define CPWAIT0()  asm volatile("cp.async.wait_group 0;" ::: "memory")
#define LDSM4(r0, r1, r2, r3, a) \
    asm volatile("ldmatrix.sync.aligned.m8n8.x4.shared.b16 {%0,%1,%2,%3}, [%4];" \
                 : "=r"(r0), "=r"(r1), "=r"(r2), "=r"(r3) : "r"(a))
#define MMA8(d, a, b0, b1) \
    asm volatile("mma.sync.aligned.m16n8k32.row.col.s32.s8.s8.s32 " \
                 "{%0,%1,%2,%3}, {%4,%5,%6,%7}, {%8,%9}, {%0,%1,%2,%3};" \
                 : "+r"((d)[0]), "+r"((d)[1]), "+r"((d)[2]), "+r"((d)[3]) \
                 : "r"((a)[0]), "r"((a)[1]), "r"((a)[2]), "r"((a)[3]), \
                   "r"(b0), "r"(b1))

// ---------------- zero BN accumulators -------------------------------------
__global__ void zero_sums_kernel() {
    int j = threadIdx.x;
    if (j < HID) { g_sum[j] = 0; g_sumsq[j] = 0; }
}

// ---------------- fp32 -> sign int8 (+1 / -1) ------------------------------
__device__ __forceinline__ uint32_t sgn4(float4 f) {
    uint32_t m = 0;
    if (f.x < 0.f) m |= 0x000000FEu;
    if (f.y < 0.f) m |= 0x0000FE00u;
    if (f.z < 0.f) m |= 0x00FE0000u;
    if (f.w < 0.f) m |= 0xFE000000u;
    return 0x01010101u ^ m;     // bytes: +1 (0x01) or -1 (0xFF)
}
__global__ __launch_bounds__(256) void pack_kernel(const float* __restrict__ src,
                                                   int8_t* __restrict__ dst) {
    size_t u = (size_t)blockIdx.x * 256 + threadIdx.x;   // 16 floats per thread
    const float4* s = reinterpret_cast<const float4*>(src) + u * 4;
    float4 f0 = s[0], f1 = s[1], f2 = s[2], f3 = s[3];
    reinterpret_cast<uint4*>(dst)[u] =
        make_uint4(sgn4(f0), sgn4(f1), sgn4(f2), sgn4(f3));
}

// ---------------- int8 mma.sync GEMM: h = xb @ wb^T -------------------------
// grid = 128 CTAs (M tiles of 64), 256 threads, full K per CTA, 3-stage cp.async.
__global__ __launch_bounds__(256, 1) void gemm_imma_kernel() {
    extern __shared__ char smem[];
    const uint32_t sb = smem_u32(smem);
    const int tid  = threadIdx.x;
    const int lane = tid & 31;
    const int wid  = tid >> 5;
    const int wm   = wid >> 2;      // 0..1  (M warp row, 32 rows each)
    const int wn   = wid & 3;       // 0..3  (N warp col, 96 cols each)
    const int m0   = blockIdx.x * CTA_M;

    // ldmatrix per-lane address offsets (within a stage)
    const int aLane = ((lane & 15) + wm * 32) * RS + ((lane >> 4) & 1) * 16;
    const int bLane = A_ST + ((lane & 7) + ((lane >> 4) & 1) * 8 + wn * 96) * RS
                      + ((lane >> 3) & 1) * 16;

    int acc[2][12][4];
#pragma unroll
    for (int i = 0; i < 2; i++)
#pragma unroll
        for (int j = 0; j < 12; j++)
#pragma unroll
            for (int k = 0; k < 4; k++) acc[i][j][k] = 0;

    // stage fill via cp.async (A: 64x128B, B: 384x128B)
    auto fill = [&](int st, int ko) {
        uint32_t base = sb + st * STAGE;
#pragma unroll
        for (int q = 0; q < 2; q++) {
            int u = tid + 256 * q, r = u >> 3, c = u & 7;
            CP16(base + r * RS + c * 16,
                 (const void*)(g_xb + (size_t)(m0 + r) * IN_F + ko + c * 16));
        }
#pragma unroll
        for (int q = 0; q < 12; q++) {
            int u = tid + 256 * q, r = u >> 3, c = u & 7;
            CP16(base + A_ST + r * RS + c * 16,
                 (const void*)(g_wb + (size_t)r * IN_F + ko + c * 16));
        }
    };

    fill(0, 0);  CPCOMMIT();
    fill(1, KD); CPCOMMIT();

    for (int it = 0; it < NS; it++) {
        const int fs = it + 2;
        if (fs < NS) { fill(fs % NSTG, fs * KD); CPCOMMIT(); CPWAIT2(); }
        else         { CPWAIT0(); }
        __syncthreads();

        const uint32_t stb = sb + (it % NSTG) * STAGE;
#pragma unroll
        for (int ks = 0; ks < 4; ks++) {
            const int kb = ks * 32;
            uint32_t a0[4], a1[4];
            LDSM4(a0[0], a0[1], a0[2], a0[3], stb + aLane + kb);
            LDSM4(a1[0], a1[1], a1[2], a1[3], stb + aLane + 16 * RS + kb);
#pragma unroll
            for (int ng = 0; ng < 6; ng++) {
                uint32_t b[4];
                LDSM4(b[0], b[1], b[2], b[3], stb + bLane + ng * (16 * RS) + kb);
                MMA8(acc[0][2 * ng],     a0, b[0], b[1]);
                MMA8(acc[0][2 * ng + 1], a0, b[2], b[3]);
                MMA8(acc[1][2 * ng],     a1, b[0], b[1]);
                MMA8(acc[1][2 * ng + 1], a1, b[2], b[3]);
            }
        }
        __syncthreads();
    }

    // epilogue: c-frag -> s16 pairs
#pragma unroll
    for (int mt = 0; mt < 2; mt++) {
        const int r0 = m0 + wm * 32 + mt * 16 + (lane >> 2);
#pragma unroll
        for (int nt = 0; nt < 12; nt++) {
            const int c = wn * 96 + nt * 8 + (lane & 3) * 2;
            const int* p = acc[mt][nt];
            *reinterpret_cast<uint32_t*>(g_h + (size_t)r0 * HID + c) =
                (p[0] & 0xFFFFu) | ((uint32_t)p[1] << 16);
            *reinterpret_cast<uint32_t*>(g_h + (size_t)(r0 + 8) * HID + c) =
                (p[2] & 0xFFFFu) | ((uint32_t)p[3] << 16);
        }
    }
}

// ---------------- BN batch statistics (exact integer sums) -----------------
__global__ void stats_kernel() {
    const int cg = blockIdx.x, rc = blockIdx.y;
    const int c = threadIdx.x & 31, t = threadIdx.x >> 5;
    const int col = cg * 32 + c;
    int s = 0;
    long long s2 = 0;
    const int rbase = rc * 1024;
    for (int r = rbase + t; r < rbase + 1024; r += 8) {
        int v = g_h[(size_t)r * HID + col];
        s += v;
        s2 += (long long)v * v;
    }
    __shared__ int       ss [8][32];
    __shared__ long long ss2[8][32];
    ss[t][c] = s; ss2[t][c] = s2;
    __syncthreads();
    if (t == 0) {
        long long S = 0, S2 = 0;
#pragma unroll
        for (int u = 0; u < 8; u++) { S += ss[u][c]; S2 += ss2[u][c]; }
        atomicAdd((unsigned long long*)&g_sum[col],   (unsigned long long)S);
        atomicAdd((unsigned long long*)&g_sumsq[col], (unsigned long long)S2);
    }
}

// ---------------- fold BN into affine --------------------------------------
__global__ void finalize_kernel(const float* __restrict__ gamma,
                                const float* __restrict__ beta) {
    int j = threadIdx.x;
    if (j >= HID) return;
    double mean = (double)g_sum[j]   / (double)BATCH;
    double var  = (double)g_sumsq[j] / (double)BATCH - mean * mean;
    float a = gamma[j] * (float)(1.0 / sqrt(var + 1e-5));
    g_A[j] = a;
    g_B[j] = beta[j] - (float)mean * a;
}

// ---------------- output layer ---------------------------------------------
__global__ __launch_bounds__(256) void out_kernel(const float* __restrict__ W4,
                                                  float* __restrict__ out) {
    int gt = blockIdx.x * blockDim.x + threadIdx.x;
    int row = gt >> 5, lane = gt & 31;
    if (row >= BATCH) return;
    float acc[NOUT];
#pragma unroll
    for (int o = 0; o < NOUT; o++) acc[o] = 0.f;
    for (int j = lane; j < HID; j += 32) {
        int hv = g_h[(size_t)row * HID + j];
        float v = (float)hv * g_A[j] + g_B[j];
        float s = (v > 0.f) ? 1.f : ((v < 0.f) ? -1.f : 0.f);
#pragma unroll
        for (int o = 0; o < NOUT; o++) {
            float w = __ldg(&W4[o * HID + j]);
            float ws = (w > 0.f) ? 1.f : ((w < 0.f) ? -1.f : 0.f);
            acc[o] = fmaf(s, ws, acc[o]);
        }
    }
#pragma unroll
    for (int o = 0; o < NOUT; o++)
#pragma unroll
        for (int off = 16; off; off >>= 1)
            acc[o] += __shfl_down_sync(0xffffffffu, acc[o], off);
    if (lane == 0) {
#pragma unroll
        for (int o = 0; o < NOUT; o++) out[(size_t)row * NOUT + o] = acc[o];
    }
}

// ---------------- launch ----------------------------------------------------
extern "C" void kernel_launch(void* const* d_in, const int* in_sizes, int n_in,
                              void* d_out, int out_size) {
    const float* x     = (const float*)d_in[0];
    const float* W1    = (const float*)d_in[1];
    const float* gamma = (const float*)d_in[2];
    const float* beta  = (const float*)d_in[3];
    const float* W4    = (const float*)d_in[4];
    float* out = (float*)d_out;

    int8_t* xb; cudaGetSymbolAddress((void**)&xb, g_xb);
    int8_t* wb; cudaGetSymbolAddress((void**)&wb, g_wb);

    zero_sums_kernel<<<1, HID>>>();
    pack_kernel<<<(BATCH * IN_F / 16) / 256, 256>>>(x, xb);   // 32768 blocks
    pack_kernel<<<(HID * IN_F / 16) / 256, 256>>>(W1, wb);    // 1536 blocks

    static int smem_set = 0;
    if (!smem_set) {
        cudaFuncSetAttribute(gemm_imma_kernel,
                             cudaFuncAttributeMaxDynamicSharedMemorySize, SMEMSZ);
        smem_set = 1;
    }
    gemm_imma_kernel<<<BATCH / CTA_M, 256, SMEMSZ>>>();       // 128 CTAs

    stats_kernel<<<dim3(HID / 32, BATCH / 1024), 256>>>();
    finalize_kernel<<<1, HID>>>(gamma, beta);
    out_kernel<<<(BATCH * 32) / 256, 256>>>(W4, out);
}

// round 5
// speedup vs baseline: 1.9248x; 1.9248x over previous
#include <cuda_runtime.h>
#include <stdint.h>

#define BATCH 8192
#define IN_F  16384
#define HID   384
#define NOUT  10
#define KW    (IN_F / 32)      // 512 k-words total
#define KWC   32               // k-words per chunk
#define NCH   (KW / KWC)       // 16 chunks
#define CTA_M 32

// smem: Bs[2][KWC*384] (2*48KB) then As[2][KWC*32] (2*4KB)
#define B_CH_W   (KWC * HID)           // 12288 words
#define A_CH_W   (KWC * CTA_M)         // 1024 words
#define SMEMSZ   (2 * B_CH_W * 4 + 2 * A_CH_W * 4)   // 106496 B

// ---------------- scratch globals ------------------------------------------
__device__ uint32_t  g_wbt[(size_t)KW * HID];   // W1 sign bits, [kword][hid]
__device__ short     g_h[(size_t)BATCH * HID];
__device__ long long g_sum[HID];
__device__ long long g_sumsq[HID];
__device__ float     g_A[HID];
__device__ float     g_B[HID];

// ---------------- PTX helpers ----------------------------------------------
__device__ __forceinline__ uint32_t smem_u32(const void* p) {
    uint32_t a;
    asm("{ .reg .u64 t; cvta.to.shared.u64 t, %1; cvt.u32.u64 %0, t; }"
        : "=r"(a) : "l"(p));
    return a;
}
#define CP16(s, g) \
    asm volatile("{ .reg .u64 gp; cvta.to.global.u64 gp, %1; " \
                 "cp.async.cg.shared.global [%0], [gp], 16; }" \
                 :: "r"(s), "l"(g) : "memory")
#define CPCOMMIT() asm volatile("cp.async.commit_group;" ::: "memory")
#define CPWAIT0()  asm volatile("cp.async.wait_group 0;" ::: "memory")
#define LDS4(r, a) \
    asm volatile("ld.shared.v4.b32 {%0,%1,%2,%3}, [%4];" \
                 : "=r"((r)[0]), "=r"((r)[1]), "=r"((r)[2]), "=r"((r)[3]) : "r"(a))

// ---------------- zero BN accumulators -------------------------------------
__global__ void zero_sums_kernel() {
    int j = threadIdx.x;
    if (j < HID) { g_sum[j] = 0; g_sumsq[j] = 0; }
}

// ---------------- W1 -> sign bits, transposed [kword][hid] ------------------
// One warp per 128 consecutive floats of one W1 row; ballot bit l = lane l.
// Element of kword (q*4+j), bit l  <->  W1[r, q*128 + 4*l + j].
__global__ __launch_bounds__(256) void packw_kernel(const float* __restrict__ W1) {
    int gw   = (blockIdx.x * 256 + threadIdx.x) >> 5;
    int lane = threadIdx.x & 31;
    int r = gw >> 7;          // 0..383
    int q = gw & 127;         // 0..127
    float4 f = *reinterpret_cast<const float4*>(W1 + (size_t)r * IN_F + q * 128 + lane * 4);
    unsigned b0 = __ballot_sync(0xffffffffu, f.x < 0.f);
    unsigned b1 = __ballot_sync(0xffffffffu, f.y < 0.f);
    unsigned b2 = __ballot_sync(0xffffffffu, f.z < 0.f);
    unsigned b3 = __ballot_sync(0xffffffffu, f.w < 0.f);
    if (lane == 0) {
        g_wbt[(size_t)(q * 4 + 0) * HID + r] = b0;
        g_wbt[(size_t)(q * 4 + 1) * HID + r] = b1;
        g_wbt[(size_t)(q * 4 + 2) * HID + r] = b2;
        g_wbt[(size_t)(q * 4 + 3) * HID + r] = b3;
    }
}

// ---------------- CSA popcount GEMM, fused sign(x) --------------------------
// 256 CTAs: M=32 rows each, N=384, full K. Warp w: rows 4w..4w+3.
// Lane n: cols 12n..12n+11. 48 cells/thread with ones-CSA + carry popcount.
__global__ __launch_bounds__(256, 1) void gemm_pop_kernel(const float* __restrict__ x) {
    extern __shared__ uint32_t smem[];
    const uint32_t sb  = smem_u32(smem);
    const int tid  = threadIdx.x;
    const int wid  = tid >> 5;
    const int lane = tid & 31;
    const int m0   = blockIdx.x * CTA_M;

    uint32_t ones[4][12];
    int      acc [4][12];
#pragma unroll
    for (int i = 0; i < 4; i++)
#pragma unroll
        for (int j = 0; j < 12; j++) { ones[i][j] = 0u; acc[i][j] = 0; }

    // B chunk loader: straight 48KB cp.async copy
    auto loadB = [&](int c, int buf) {
        const char* src = (const char*)g_wbt + (size_t)c * (B_CH_W * 4);
        uint32_t dst = sb + buf * (B_CH_W * 4);
#pragma unroll
        for (int i = 0; i < 12; i++) {
            int u = tid + 256 * i;
            CP16(dst + u * 16, src + (size_t)u * 16);
        }
    };
    // A chunk: read x fp32, binarize via ballot, STS bit-words [kw][row]
    auto convA = [&](int c, int buf) {
        uint32_t* As = smem + 2 * B_CH_W + buf * A_CH_W;
#pragma unroll 4
        for (int t = 0; t < 32; t++) {
            int G = wid * 32 + t;
            int row = G >> 3, gcol = G & 7;
            float4 f = *reinterpret_cast<const float4*>(
                x + (size_t)(m0 + row) * IN_F + c * (KWC * 32) + gcol * 128 + lane * 4);
            unsigned b0 = __ballot_sync(0xffffffffu, f.x < 0.f);
            unsigned b1 = __ballot_sync(0xffffffffu, f.y < 0.f);
            unsigned b2 = __ballot_sync(0xffffffffu, f.z < 0.f);
            unsigned b3 = __ballot_sync(0xffffffffu, f.w < 0.f);
            if (lane == 0) {
                As[(gcol * 4 + 0) * CTA_M + row] = b0;
                As[(gcol * 4 + 1) * CTA_M + row] = b1;
                As[(gcol * 4 + 2) * CTA_M + row] = b2;
                As[(gcol * 4 + 3) * CTA_M + row] = b3;
            }
        }
    };

    loadB(0, 0); CPCOMMIT();
    convA(0, 0);
    CPWAIT0(); __syncthreads();

    for (int c = 0; c < NCH; c++) {
        const int buf = c & 1;
        if (c + 1 < NCH) { loadB(c + 1, buf ^ 1); CPCOMMIT(); convA(c + 1, buf ^ 1); }

        const uint32_t bB = sb + buf * (B_CH_W * 4);
        const uint32_t bA = sb + 2 * (B_CH_W * 4) + buf * (A_CH_W * 4);
        for (int kp = 0; kp < KWC / 2; kp++) {
            uint32_t a0[4], a1[4], b0[12], b1[12];
            LDS4(a0, bA + (2 * kp) * (CTA_M * 4) + wid * 16);
            LDS4(a1, bA + (2 * kp + 1) * (CTA_M * 4) + wid * 16);
            LDS4(&b0[0], bB + (2 * kp) * (HID * 4) + lane * 48);
            LDS4(&b0[4], bB + (2 * kp) * (HID * 4) + lane * 48 + 16);
            LDS4(&b0[8], bB + (2 * kp) * (HID * 4) + lane * 48 + 32);
            LDS4(&b1[0], bB + (2 * kp + 1) * (HID * 4) + lane * 48);
            LDS4(&b1[4], bB + (2 * kp + 1) * (HID * 4) + lane * 48 + 16);
            LDS4(&b1[8], bB + (2 * kp + 1) * (HID * 4) + lane * 48 + 32);
#pragma unroll
            for (int i = 0; i < 4; i++)
#pragma unroll
                for (int j = 0; j < 12; j++) {
                    uint32_t u = a0[i] ^ b0[j];
                    uint32_t v = a1[i] ^ b1[j];
                    uint32_t o = ones[i][j];
                    uint32_t cy = (o & u) | (o & v) | (u & v);  // 1x LOP3 maj
                    ones[i][j] = o ^ u ^ v;                     // 1x LOP3 xor3
                    acc[i][j] += __popc(cy);
                }
        }
        if (c + 1 < NCH) CPWAIT0();
        __syncthreads();
    }

    // h = IN_F - 2*mismatch, mismatch = 2*acc + popc(ones)
#pragma unroll
    for (int i = 0; i < 4; i++) {
        const int row = m0 + wid * 4 + i;
        short2* dst = reinterpret_cast<short2*>(g_h + (size_t)row * HID + lane * 12);
#pragma unroll
        for (int jp = 0; jp < 6; jp++) {
            int t0 = 2 * acc[i][2 * jp]     + __popc(ones[i][2 * jp]);
            int t1 = 2 * acc[i][2 * jp + 1] + __popc(ones[i][2 * jp + 1]);
            dst[jp] = make_short2((short)(IN_F - 2 * t0), (short)(IN_F - 2 * t1));
        }
    }
}

// ---------------- BN batch statistics (exact integer sums) -----------------
__global__ void stats_kernel() {
    const int cg = blockIdx.x, rc = blockIdx.y;
    const int c = threadIdx.x & 31, t = threadIdx.x >> 5;
    const int col = cg * 32 + c;
    int s = 0;
    long long s2 = 0;
    const int rbase = rc * 1024;
    for (int r = rbase + t; r < rbase + 1024; r += 8) {
        int v = g_h[(size_t)r * HID + col];
        s += v;
        s2 += (long long)v * v;
    }
    __shared__ int       ss [8][32];
    __shared__ long long ss2[8][32];
    ss[t][c] = s; ss2[t][c] = s2;
    __syncthreads();
    if (t == 0) {
        long long S = 0, S2 = 0;
#pragma unroll
        for (int u = 0; u < 8; u++) { S += ss[u][c]; S2 += ss2[u][c]; }
        atomicAdd((unsigned long long*)&g_sum[col],   (unsigned long long)S);
        atomicAdd((unsigned long long*)&g_sumsq[col], (unsigned long long)S2);
    }
}

// ---------------- fold BN into affine --------------------------------------
__global__ void finalize_kernel(const float* __restrict__ gamma,
                                const float* __restrict__ beta) {
    int j = threadIdx.x;
    if (j >= HID) return;
    double mean = (double)g_sum[j]   / (double)BATCH;
    double var  = (double)g_sumsq[j] / (double)BATCH - mean * mean;
    float a = gamma[j] * (float)(1.0 / sqrt(var + 1e-5));
    g_A[j] = a;
    g_B[j] = beta[j] - (float)mean * a;
}

// ---------------- output layer ---------------------------------------------
__global__ __launch_bounds__(256) void out_kernel(const float* __restrict__ W4,
                                                  float* __restrict__ out) {
    int gt = blockIdx.x * blockDim.x + threadIdx.x;
    int row = gt >> 5, lane = gt & 31;
    if (row >= BATCH) return;
    float acc[NOUT];
#pragma unroll
    for (int o = 0; o < NOUT; o++) acc[o] = 0.f;
    for (int j = lane; j < HID; j += 32) {
        int hv = g_h[(size_t)row * HID + j];
        float v = (float)hv * g_A[j] + g_B[j];
        float s = (v > 0.f) ? 1.f : ((v < 0.f) ? -1.f : 0.f);
#pragma unroll
        for (int o = 0; o < NOUT; o++) {
            float w = __ldg(&W4[o * HID + j]);
            float ws = (w > 0.f) ? 1.f : ((w < 0.f) ? -1.f : 0.f);
            acc[o] = fmaf(s, ws, acc[o]);
        }
    }
#pragma unroll
    for (int o = 0; o < NOUT; o++)
#pragma unroll
        for (int off = 16; off; off >>= 1)
            acc[o] += __shfl_down_sync(0xffffffffu, acc[o], off);
    if (lane == 0) {
#pragma unroll
        for (int o = 0; o < NOUT; o++) out[(size_t)row * NOUT + o] = acc[o];
    }
}

// ---------------- launch ----------------------------------------------------
extern "C" void kernel_launch(void* const* d_in, const int* in_sizes, int n_in,
                              void* d_out, int out_size) {
    const float* x     = (const float*)d_in[0];
    const float* W1    = (const float*)d_in[1];
    const float* gamma = (const float*)d_in[2];
    const float* beta  = (const float*)d_in[3];
    const float* W4    = (const float*)d_in[4];
    float* out = (float*)d_out;

    zero_sums_kernel<<<1, HID>>>();
    packw_kernel<<<(HID * 128) / 8, 256>>>(W1);   // 6144 blocks

    cudaFuncSetAttribute(gemm_pop_kernel,
                         cudaFuncAttributeMaxDynamicSharedMemorySize, SMEMSZ);
    gemm_pop_kernel<<<BATCH / CTA_M, 256, SMEMSZ>>>(x);   // 256 CTAs

    stats_kernel<<<dim3(HID / 32, BATCH / 1024), 256>>>();
    finalize_kernel<<<1, HID>>>(gamma, beta);
    out_kernel<<<(BATCH * 32) / 256, 256>>>(W4, out);
}

// round 7
// speedup vs baseline: 1.9884x; 1.0330x over previous
#include <cuda_runtime.h>
#include <stdint.h>

#define BATCH 8192
#define IN_F  16384
#define HID   384
#define NOUT  10
#define KW    (IN_F / 32)      // 512 k-words total
#define KWC   16               // k-words per chunk
#define NCH   (KW / KWC)       // 32 chunks
#define CTA_M 16
#define NTHR  128

#define B_CH_W (KWC * HID)     // 6144 words = 24KB
#define A_CH_W (KWC * CTA_M)   // 256 words = 1KB
#define B_BYTES (B_CH_W * 4)
#define A_BYTES (A_CH_W * 4)
#define SMEMSZ  (2 * (B_BYTES + A_BYTES))   // 51200 B

// ---------------- scratch globals ------------------------------------------
__device__ uint32_t  g_wbt[(size_t)KW * HID];   // W1 sign bits, [kword][hid]
__device__ short     g_h[(size_t)BATCH * HID];
__device__ long long g_sum[HID];
__device__ long long g_sumsq[HID];
__device__ float     g_A[HID];
__device__ float     g_B[HID];

// ---------------- PTX helpers ----------------------------------------------
__device__ __forceinline__ uint32_t smem_u32(const void* p) {
    uint32_t a;
    asm("{ .reg .u64 t; cvta.to.shared.u64 t, %1; cvt.u32.u64 %0, t; }"
        : "=r"(a) : "l"(p));
    return a;
}
#define CP16(s, g) \
    asm volatile("{ .reg .u64 gp; cvta.to.global.u64 gp, %1; " \
                 "cp.async.cg.shared.global [%0], [gp], 16; }" \
                 :: "r"(s), "l"(g) : "memory")
#define CPCOMMIT() asm volatile("cp.async.commit_group;" ::: "memory")
#define CPWAIT0()  asm volatile("cp.async.wait_group 0;" ::: "memory")
#define LDS4(r, a) \
    asm volatile("ld.shared.v4.b32 {%0,%1,%2,%3}, [%4];" \
                 : "=r"((r)[0]), "=r"((r)[1]), "=r"((r)[2]), "=r"((r)[3]) : "r"(a))

// ---------------- zero BN accumulators -------------------------------------
__global__ void zero_sums_kernel() {
    int j = threadIdx.x;
    if (j < HID) { g_sum[j] = 0; g_sumsq[j] = 0; }
}

// ---------------- W1 -> sign bits, transposed [kword][hid] ------------------
// kword (q*4+j), bit l  <->  W1[r, q*128 + 4*l + j]   (same perm used for x)
__global__ __launch_bounds__(256) void packw_kernel(const float* __restrict__ W1) {
    int gw   = (blockIdx.x * 256 + threadIdx.x) >> 5;
    int lane = threadIdx.x & 31;
    int r = gw >> 7;          // 0..383
    int q = gw & 127;         // 0..127
    float4 f = *reinterpret_cast<const float4*>(W1 + (size_t)r * IN_F + q * 128 + lane * 4);
    unsigned b0 = __ballot_sync(0xffffffffu, f.x < 0.f);
    unsigned b1 = __ballot_sync(0xffffffffu, f.y < 0.f);
    unsigned b2 = __ballot_sync(0xffffffffu, f.z < 0.f);
    unsigned b3 = __ballot_sync(0xffffffffu, f.w < 0.f);
    if (lane == 0) {
        g_wbt[(size_t)(q * 4 + 0) * HID + r] = b0;
        g_wbt[(size_t)(q * 4 + 1) * HID + r] = b1;
        g_wbt[(size_t)(q * 4 + 2) * HID + r] = b2;
        g_wbt[(size_t)(q * 4 + 3) * HID + r] = b3;
    }
}

// ---------------- popcount GEMM, fused sign(x), 4 CTAs/SM -------------------
// 512 CTAs: M=16 rows each, N=384, full K. Warp w: rows 4w..4w+3.
// Lane n: cols 12n..12n+11. 48 plain popcount cells per thread.
__global__ __launch_bounds__(NTHR, 4) void gemm_pop_kernel(const float* __restrict__ x) {
    extern __shared__ uint32_t smem[];
    const uint32_t sb  = smem_u32(smem);
    const int tid  = threadIdx.x;
    const int wid  = tid >> 5;
    const int lane = tid & 31;
    const int m0   = blockIdx.x * CTA_M;

    int acc[4][12];
#pragma unroll
    for (int i = 0; i < 4; i++)
#pragma unroll
        for (int j = 0; j < 12; j++) acc[i][j] = 0;

    // B chunk: 24KB cp.async copy (12 x 16B per thread)
    auto loadB = [&](int c, int buf) {
        const char* src = (const char*)g_wbt + (size_t)c * B_BYTES;
        uint32_t dst = sb + buf * B_BYTES;
#pragma unroll
        for (int i = 0; i < 12; i++) {
            int u = tid + NTHR * i;
            CP16(dst + u * 16, src + (size_t)u * 16);
        }
    };
    // A chunk: read x fp32, ballot-binarize, store [kw][row] bit-words.
    // 64 tasks (16 rows x 4 col-groups), 16 per warp.
    auto convA = [&](int c, int buf) {
        uint32_t* As = smem + 2 * B_CH_W + buf * A_CH_W;
#pragma unroll 4
        for (int t = 0; t < 16; t++) {
            int G = wid * 16 + t;
            int row = G >> 2, gcol = G & 3;
            float4 f = *reinterpret_cast<const float4*>(
                x + (size_t)(m0 + row) * IN_F + c * (KWC * 32) + gcol * 128 + lane * 4);
            unsigned b0 = __ballot_sync(0xffffffffu, f.x < 0.f);
            unsigned b1 = __ballot_sync(0xffffffffu, f.y < 0.f);
            unsigned b2 = __ballot_sync(0xffffffffu, f.z < 0.f);
            unsigned b3 = __ballot_sync(0xffffffffu, f.w < 0.f);
            if (lane == 0) {
                As[(gcol * 4 + 0) * CTA_M + row] = b0;
                As[(gcol * 4 + 1) * CTA_M + row] = b1;
                As[(gcol * 4 + 2) * CTA_M + row] = b2;
                As[(gcol * 4 + 3) * CTA_M + row] = b3;
            }
        }
    };

    loadB(0, 0); CPCOMMIT();
    convA(0, 0);
    CPWAIT0(); __syncthreads();

    for (int c = 0; c < NCH; c++) {
        const int buf = c & 1;
        if (c + 1 < NCH) { loadB(c + 1, buf ^ 1); CPCOMMIT(); convA(c + 1, buf ^ 1); }

        const uint32_t bB = sb + buf * B_BYTES;
        const uint32_t bA = sb + 2 * B_BYTES + buf * A_BYTES;
#pragma unroll 2
        for (int kw = 0; kw < KWC; kw++) {
            uint32_t a[4], b[12];
            LDS4(a, bA + kw * (CTA_M * 4) + wid * 16);             // broadcast
            LDS4(&b[0], bB + kw * (HID * 4) + lane * 48);          // conflict-free
            LDS4(&b[4], bB + kw * (HID * 4) + lane * 48 + 16);
            LDS4(&b[8], bB + kw * (HID * 4) + lane * 48 + 32);
#pragma unroll
            for (int i = 0; i < 4; i++)
#pragma unroll
                for (int j = 0; j < 12; j++)
                    acc[i][j] += __popc(a[i] ^ b[j]);
        }
        if (c + 1 < NCH) CPWAIT0();
        __syncthreads();
    }

    // h = IN_F - 2*mismatch
#pragma unroll
    for (int i = 0; i < 4; i++) {
        const int row = m0 + wid * 4 + i;
        short2* dst = reinterpret_cast<short2*>(g_h + (size_t)row * HID + lane * 12);
#pragma unroll
        for (int jp = 0; jp < 6; jp++)
            dst[jp] = make_short2((short)(IN_F - 2 * acc[i][2 * jp]),
                                  (short)(IN_F - 2 * acc[i][2 * jp + 1]));
    }
}

// ---------------- BN batch statistics (exact integer sums) -----------------
__global__ void stats_kernel() {
    const int cg = blockIdx.x, rc = blockIdx.y;
    const int c = threadIdx.x & 31, t = threadIdx.x >> 5;
    const int col = cg * 32 + c;
    int s = 0;
    long long s2 = 0;
    const int rbase = rc * 1024;
    for (int r = rbase + t; r < rbase + 1024; r += 8) {
        int v = g_h[(size_t)r * HID + col];
        s += v;
        s2 += (long long)v * v;
    }
    __shared__ int       ss [8][32];
    __shared__ long long ss2[8][32];
    ss[t][c] = s; ss2[t][c] = s2;
    __syncthreads();
    if (t == 0) {
        long long S = 0, S2 = 0;
#pragma unroll
        for (int u = 0; u < 8; u++) { S += ss[u][c]; S2 += ss2[u][c]; }
        atomicAdd((unsigned long long*)&g_sum[col],   (unsigned long long)S);
        atomicAdd((unsigned long long*)&g_sumsq[col], (unsigned long long)S2);
    }
}

// ---------------- fold BN into affine --------------------------------------
__global__ void finalize_kernel(const float* __restrict__ gamma,
                                const float* __restrict__ beta) {
    int j = threadIdx.x;
    if (j >= HID) return;
    double mean = (double)g_sum[j]   / (double)BATCH;
    double var  = (double)g_sumsq[j] / (double)BATCH - mean * mean;
    float a = gamma[j] * (float)(1.0 / sqrt(var + 1e-5));
    g_A[j] = a;
    g_B[j] = beta[j] - (float)mean * a;
}

// ---------------- output layer ---------------------------------------------
__global__ __launch_bounds__(256) void out_kernel(const float* __restrict__ W4,
                                                  float* __restrict__ out) {
    int gt = blockIdx.x * blockDim.x + threadIdx.x;
    int row = gt >> 5, lane = gt & 31;
    if (row >= BATCH) return;
    float acc[NOUT];
#pragma unroll
    for (int o = 0; o < NOUT; o++) acc[o] = 0.f;
    for (int j = lane; j < HID; j += 32) {
        int hv = g_h[(size_t)row * HID + j];
        float v = (float)hv * g_A[j] + g_B[j];
        float s = (v > 0.f) ? 1.f : ((v < 0.f) ? -1.f : 0.f);
#pragma unroll
        for (int o = 0; o < NOUT; o++) {
            float w = __ldg(&W4[o * HID + j]);
            float ws = (w > 0.f) ? 1.f : ((w < 0.f) ? -1.f : 0.f);
            acc[o] = fmaf(s, ws, acc[o]);
        }
    }
#pragma unroll
    for (int o = 0; o < NOUT; o++)
#pragma unroll
        for (int off = 16; off; off >>= 1)
            acc[o] += __shfl_down_sync(0xffffffffu, acc[o], off);
    if (lane == 0) {
#pragma unroll
        for (int o = 0; o < NOUT; o++) out[(size_t)row * NOUT + o] = acc[o];
    }
}

// ---------------- launch ----------------------------------------------------
extern "C" void kernel_launch(void* const* d_in, const int* in_sizes, int n_in,
                              void* d_out, int out_size) {
    const float* x     = (const float*)d_in[0];
    const float* W1    = (const float*)d_in[1];
    const float* gamma = (const float*)d_in[2];
    const float* beta  = (const float*)d_in[3];
    const float* W4    = (const float*)d_in[4];
    float* out = (float*)d_out;

    zero_sums_kernel<<<1, HID>>>();
    packw_kernel<<<(HID * 128) / 8, 256>>>(W1);   // 6144 blocks

    cudaFuncSetAttribute(gemm_pop_kernel,
                         cudaFuncAttributeMaxDynamicSharedMemorySize, SMEMSZ);
    gemm_pop_kernel<<<BATCH / CTA_M, NTHR, SMEMSZ>>>(x);   // 512 CTAs

    stats_kernel<<<dim3(HID / 32, BATCH / 1024), 256>>>();
    finalize_kernel<<<1, HID>>>(gamma, beta);
    out_kernel<<<(BATCH * 32) / 256, 256>>>(W4, out);
}